// round 6
// baseline (speedup 1.0000x reference)
#include <cuda_runtime.h>
#include <mma.h>
#include <math.h>

using namespace nvcuda;

#define HID    1024
#define NHEADS 16
#define HDIM   64
#define NB     2
#define SEQ    2048
#define NBH    (NB*NHEADS)
#define KKEEP  1024

#define BK      16
#define ASTRIDE 24   // BK + 8 pad

// ---------------- scratch (allocation-free: __device__ globals) ----------------
__device__ float g_q[(size_t)NBH * SEQ * HDIM];     // [B,H,S,D]
__device__ float g_k[(size_t)NBH * SEQ * HDIM];
__device__ float g_v[(size_t)NBH * SEQ * HDIM];
__device__ float g_p[(size_t)NBH * SEQ * SEQ];      // scores -> probs in place
__device__ float g_ctx[(size_t)NB * SEQ * HID];     // [B,S,H*D]

// ---------------- reduces ----------------
__device__ __forceinline__ float warp_max_f(float v) {
#pragma unroll
    for (int o = 16; o > 0; o >>= 1) v = fmaxf(v, __shfl_xor_sync(0xffffffffu, v, o));
    return v;
}
__device__ __forceinline__ float warp_sum_f(float v) {
#pragma unroll
    for (int o = 16; o > 0; o >>= 1) v += __shfl_xor_sync(0xffffffffu, v, o);
    return v;
}
__device__ __forceinline__ float block_max_f(float v, float* sm) {
    v = warp_max_f(v);
    if ((threadIdx.x & 31) == 0) sm[threadIdx.x >> 5] = v;
    __syncthreads();
    if (threadIdx.x == 0) {
        float r = sm[0];
#pragma unroll
        for (int i = 1; i < 8; i++) r = fmaxf(r, sm[i]);
        sm[0] = r;
    }
    __syncthreads();
    v = sm[0];
    __syncthreads();
    return v;
}
__device__ __forceinline__ float block_sum_f(float v, float* sm) {
    v = warp_sum_f(v);
    if ((threadIdx.x & 31) == 0) sm[threadIdx.x >> 5] = v;
    __syncthreads();
    if (threadIdx.x == 0) {
        float r = sm[0];
#pragma unroll
        for (int i = 1; i < 8; i++) r += sm[i];
        sm[0] = r;
    }
    __syncthreads();
    v = sm[0];
    __syncthreads();
    return v;
}

// ===================================================================
// 3xTF32 WMMA NT GEMM core: C(128x128) += A[M,K](rm) * B[N,K](rm)^T
// hi/lo split on register fragments; c += a_hi*b_lo + a_lo*b_hi + a_hi*b_hi.
// 256 threads = 8 warps (4m x 2n); warp tile 32x64; BK=16 double-buffered.
// ===================================================================
typedef wmma::fragment<wmma::accumulator, 16, 16, 8, float> AccFrag;
typedef wmma::fragment<wmma::matrix_a, 16, 16, 8, wmma::precision::tf32, wmma::row_major> AFrag;
typedef wmma::fragment<wmma::matrix_b, 16, 16, 8, wmma::precision::tf32, wmma::col_major> BFragCol;
typedef wmma::fragment<wmma::matrix_b, 16, 16, 8, wmma::precision::tf32, wmma::row_major> BFragRow;

template <class Frag>
__device__ __forceinline__ void split_frag(Frag& hi, Frag& lo) {
#pragma unroll
    for (int t = 0; t < hi.num_elements; t++) {
        float f = hi.x[t];
        float h = wmma::__float_to_tf32(f);
        lo.x[t] = wmma::__float_to_tf32(f - h);
        hi.x[t] = h;
    }
}

__device__ __forceinline__ void nt_wmma_gemm(
    const float* __restrict__ A, const float* __restrict__ B, int K,
    int m0, int n0, AccFrag c[2][4])
{
    __shared__ float As[2][128][ASTRIDE];
    __shared__ float Bs[2][128][ASTRIDE];

    int tid  = threadIdx.x;
    int warp = tid >> 5;
    int wm = warp >> 1, wn = warp & 1;

#pragma unroll
    for (int i = 0; i < 2; i++)
#pragma unroll
        for (int j = 0; j < 4; j++)
            wmma::fill_fragment(c[i][j], 0.0f);

    int r0 = (tid + 0)   >> 2, c0 = ((tid + 0)   & 3) << 2;
    int r1 = (tid + 256) >> 2, c1 = ((tid + 256) & 3) << 2;

    {
        float4 a0 = *(const float4*)(A + (size_t)(m0 + r0) * K + c0);
        float4 a1 = *(const float4*)(A + (size_t)(m0 + r1) * K + c1);
        float4 b0 = *(const float4*)(B + (size_t)(n0 + r0) * K + c0);
        float4 b1 = *(const float4*)(B + (size_t)(n0 + r1) * K + c1);
        *(float4*)&As[0][r0][c0] = a0; *(float4*)&As[0][r1][c1] = a1;
        *(float4*)&Bs[0][r0][c0] = b0; *(float4*)&Bs[0][r1][c1] = b1;
    }
    __syncthreads();

    const int nk = K / BK;
    for (int kt = 0; kt < nk; kt++) {
        int cur = kt & 1;
        float4 an0, an1, bn0, bn1;
        if (kt + 1 < nk) {
            int k0 = (kt + 1) * BK;
            an0 = *(const float4*)(A + (size_t)(m0 + r0) * K + k0 + c0);
            an1 = *(const float4*)(A + (size_t)(m0 + r1) * K + k0 + c1);
            bn0 = *(const float4*)(B + (size_t)(n0 + r0) * K + k0 + c0);
            bn1 = *(const float4*)(B + (size_t)(n0 + r1) * K + k0 + c1);
        }
#pragma unroll
        for (int ks = 0; ks < 2; ks++) {
            AFrag a_hi[2], a_lo[2];
            BFragCol b_hi[4], b_lo[4];
#pragma unroll
            for (int i = 0; i < 2; i++) {
                wmma::load_matrix_sync(a_hi[i], &As[cur][wm * 32 + i * 16][ks * 8], ASTRIDE);
                split_frag(a_hi[i], a_lo[i]);
            }
#pragma unroll
            for (int j = 0; j < 4; j++) {
                wmma::load_matrix_sync(b_hi[j], &Bs[cur][wn * 64 + j * 16][ks * 8], ASTRIDE);
                split_frag(b_hi[j], b_lo[j]);
            }
#pragma unroll
            for (int i = 0; i < 2; i++)
#pragma unroll
                for (int j = 0; j < 4; j++) {
                    wmma::mma_sync(c[i][j], a_hi[i], b_lo[j], c[i][j]);
                    wmma::mma_sync(c[i][j], a_lo[i], b_hi[j], c[i][j]);
                    wmma::mma_sync(c[i][j], a_hi[i], b_hi[j], c[i][j]);
                }
        }
        if (kt + 1 < nk) {
            int nxt = cur ^ 1;
            *(float4*)&As[nxt][r0][c0] = an0; *(float4*)&As[nxt][r1][c1] = an1;
            *(float4*)&Bs[nxt][r0][c0] = bn0; *(float4*)&Bs[nxt][r1][c1] = bn1;
            __syncthreads();
        }
    }
}

// ---------------- GEMM 1: QKV projection -> scatter [B,H,S,D] ----------------
__global__ void __launch_bounds__(256) proj_kernel(const float* __restrict__ x,
                                                   const float* __restrict__ Wq,
                                                   const float* __restrict__ Wk,
                                                   const float* __restrict__ Wv) {
    const float* W;
    float* outp;
    if (blockIdx.z == 0)      { W = Wq; outp = g_q; }
    else if (blockIdx.z == 1) { W = Wk; outp = g_k; }
    else                      { W = Wv; outp = g_v; }

    int m0 = blockIdx.y * 128, n0 = blockIdx.x * 128;
    AccFrag c[2][4];
    nt_wmma_gemm(x, W, HID, m0, n0, c);

    int warp = threadIdx.x >> 5;
    int wm = warp >> 1, wn = warp & 1;
    int h = (n0 + wn * 64) >> 6;          // warp's 64-col span = one head
#pragma unroll
    for (int i = 0; i < 2; i++) {
        int mm = m0 + wm * 32 + i * 16;
        int b = mm >> 11, s = mm & (SEQ - 1);
        float* base = outp + (((size_t)(b * NHEADS + h) * SEQ + s) * HDIM);
#pragma unroll
        for (int j = 0; j < 4; j++)
            wmma::store_matrix_sync(base + j * 16, c[i][j], HDIM, wmma::mem_row_major);
    }
}

// ---------------- GEMM 2: scores = Q K^T / 8 per (b,h) ----------------
__global__ void __launch_bounds__(256) scores_kernel() {
    int bh = blockIdx.z;
    const float* A  = g_q + (size_t)bh * SEQ * HDIM;
    const float* Bm = g_k + (size_t)bh * SEQ * HDIM;
    float* C = g_p + (size_t)bh * SEQ * SEQ;

    int m0 = blockIdx.y * 128, n0 = blockIdx.x * 128;
    AccFrag c[2][4];
    nt_wmma_gemm(A, Bm, HDIM, m0, n0, c);

    int warp = threadIdx.x >> 5;
    int wm = warp >> 1, wn = warp & 1;
#pragma unroll
    for (int i = 0; i < 2; i++) {
        int mm = m0 + wm * 32 + i * 16;
#pragma unroll
        for (int j = 0; j < 4; j++) {
#pragma unroll
            for (int t = 0; t < c[i][j].num_elements; t++) c[i][j].x[t] *= 0.125f;
            wmma::store_matrix_sync(C + (size_t)mm * SEQ + n0 + wn * 64 + j * 16,
                                    c[i][j], SEQ, wmma::mem_row_major);
        }
    }
}

// ---------------- GEMM 4: out = ctx @ Wo^T (bias added separately) ----------------
__global__ void __launch_bounds__(256) final_kernel(const float* __restrict__ Wo,
                                                    float* __restrict__ out) {
    int m0 = blockIdx.y * 128, n0 = blockIdx.x * 128;
    AccFrag c[2][4];
    nt_wmma_gemm(g_ctx, Wo, HID, m0, n0, c);

    int warp = threadIdx.x >> 5;
    int wm = warp >> 1, wn = warp & 1;
#pragma unroll
    for (int i = 0; i < 2; i++) {
        int mm = m0 + wm * 32 + i * 16;
#pragma unroll
        for (int j = 0; j < 4; j++)
            wmma::store_matrix_sync(out + (size_t)mm * HID + n0 + wn * 64 + j * 16,
                                    c[i][j], HID, wmma::mem_row_major);
    }
}

__global__ void bias_kernel(float* __restrict__ out, const float* __restrict__ bo) {
    int i = blockIdx.x * blockDim.x + threadIdx.x;   // float4 index
    float4 v = ((float4*)out)[i];
    float4 b = ((const float4*)bo)[i & 255];
    v.x += b.x; v.y += b.y; v.z += b.z; v.w += b.w;
    ((float4*)out)[i] = v;
}

// ---------------- kernel 3: exact top-k(1024) + threshold + masked softmax ----------------
__global__ void __launch_bounds__(256) topk_softmax_kernel(const float* __restrict__ thr_ptr) {
    __shared__ unsigned hist[2048];
    __shared__ unsigned chunk[257];
    __shared__ float smf[8];
    __shared__ unsigned s_bin, s_kr;

    size_t row = blockIdx.x;
    float* p = g_p + row * SEQ;
    int tid = threadIdx.x;

    float v[8];
    unsigned key[8];
    bool act[8];
#pragma unroll
    for (int i = 0; i < 8; i++) {
        v[i] = p[tid + (i << 8)];
        unsigned bb = __float_as_uint(v[i]);
        key[i] = (bb & 0x80000000u) ? ~bb : (bb | 0x80000000u);
        act[i] = true;
    }

    float lm = v[0];
#pragma unroll
    for (int i = 1; i < 8; i++) lm = fmaxf(lm, v[i]);
    float m = block_max_f(lm, smf);

    unsigned Kr = KKEEP;
    unsigned prefixKey = 0;

#pragma unroll
    for (int lvl = 0; lvl < 3; lvl++) {
        const int shift = (lvl == 0) ? 21 : (lvl == 1) ? 10 : 0;
        const unsigned mask = (lvl == 2) ? 1023u : 2047u;

        for (int i = tid; i < 2048; i += 256) hist[i] = 0u;
        __syncthreads();
#pragma unroll
        for (int i = 0; i < 8; i++)
            if (act[i]) atomicAdd(&hist[(key[i] >> shift) & mask], 1u);
        __syncthreads();

        unsigned cs = 0;
#pragma unroll
        for (int j = 0; j < 8; j++) cs += hist[(tid << 3) + j];
        chunk[tid] = cs;
        if (tid == 0) chunk[256] = 0u;
        __syncthreads();

        for (int off = 1; off < 256; off <<= 1) {
            unsigned add = (tid + off < 256) ? chunk[tid + off] : 0u;
            __syncthreads();
            chunk[tid] += add;
            __syncthreads();
        }

        unsigned sfx  = chunk[tid];
        unsigned sfxn = chunk[tid + 1];
        if (sfx >= Kr && sfxn < Kr) {
            unsigned cum = sfxn;
#pragma unroll
            for (int j = 7; j >= 0; j--) {
                unsigned h = hist[(tid << 3) + j];
                cum += h;
                if (cum >= Kr) {
                    s_bin = (tid << 3) + j;
                    s_kr  = Kr - (cum - h);
                    break;
                }
            }
        }
        __syncthreads();
        unsigned b = s_bin;
        Kr = s_kr;
        prefixKey |= b << shift;
        if (lvl < 2) {
#pragma unroll
            for (int i = 0; i < 8; i++)
                act[i] = act[i] && (((key[i] >> shift) & mask) == b);
        }
        __syncthreads();
    }

    float kth = __uint_as_float((prefixKey & 0x80000000u) ? (prefixKey ^ 0x80000000u)
                                                          : ~prefixKey);

    float thr = thr_ptr[0];
    thr = fminf(fmaxf(thr, 0.0f), 1.0f);
    float teff = fmaxf(kth, thr);

    float e[8];
    float ls = 0.0f;
#pragma unroll
    for (int i = 0; i < 8; i++) {
        e[i] = (v[i] >= teff) ? expf(v[i] - m) : 0.0f;
        ls += e[i];
    }
    float s = block_sum_f(ls, smf);
    float inv = 1.0f / s;
#pragma unroll
    for (int i = 0; i < 8; i++) p[tid + (i << 8)] = e[i] * inv;
}

// ---------------- GEMM 3 (NN, 3xTF32): ctx = P @ V per (b,h) ----------------
// Block tile 128x64, 8 warps (4x2), warp tile 32x32, BK=16.
#define BSTRIDE 72
__global__ void __launch_bounds__(256) av_kernel() {
    int bh = blockIdx.z;
    int b = bh >> 4, h = bh & 15;
    const float* A  = g_p + (size_t)bh * SEQ * SEQ;    // probs [S,S] rm
    const float* Bv = g_v + (size_t)bh * SEQ * HDIM;   // V [S,64] rm

    __shared__ float As[2][128][ASTRIDE];
    __shared__ float Bs[2][BK][BSTRIDE];

    int tid  = threadIdx.x;
    int warp = tid >> 5;
    int wm = warp >> 1, wn = warp & 1;
    int m0 = blockIdx.y * 128;

    AccFrag c[2][2];
#pragma unroll
    for (int i = 0; i < 2; i++)
#pragma unroll
        for (int j = 0; j < 2; j++)
            wmma::fill_fragment(c[i][j], 0.0f);

    int ar0 = (tid + 0)   >> 2, ac0 = ((tid + 0)   & 3) << 2;
    int ar1 = (tid + 256) >> 2, ac1 = ((tid + 256) & 3) << 2;
    int br_ = tid >> 4,        bc_ = (tid & 15) << 2;

    {
        float4 a0 = *(const float4*)(A + (size_t)(m0 + ar0) * SEQ + ac0);
        float4 a1 = *(const float4*)(A + (size_t)(m0 + ar1) * SEQ + ac1);
        float4 b0 = *(const float4*)(Bv + (size_t)br_ * HDIM + bc_);
        *(float4*)&As[0][ar0][ac0] = a0; *(float4*)&As[0][ar1][ac1] = a1;
        *(float4*)&Bs[0][br_][bc_] = b0;
    }
    __syncthreads();

    const int nk = SEQ / BK;
    for (int kt = 0; kt < nk; kt++) {
        int cur = kt & 1;
        float4 an0, an1, bn0;
        if (kt + 1 < nk) {
            int k0 = (kt + 1) * BK;
            an0 = *(const float4*)(A + (size_t)(m0 + ar0) * SEQ + k0 + ac0);
            an1 = *(const float4*)(A + (size_t)(m0 + ar1) * SEQ + k0 + ac1);
            bn0 = *(const float4*)(Bv + (size_t)(k0 + br_) * HDIM + bc_);
        }
#pragma unroll
        for (int ks = 0; ks < 2; ks++) {
            AFrag a_hi[2], a_lo[2];
            BFragRow b_hi[2], b_lo[2];
#pragma unroll
            for (int i = 0; i < 2; i++) {
                wmma::load_matrix_sync(a_hi[i], &As[cur][wm * 32 + i * 16][ks * 8], ASTRIDE);
                split_frag(a_hi[i], a_lo[i]);
            }
#pragma unroll
            for (int j = 0; j < 2; j++) {
                wmma::load_matrix_sync(b_hi[j], &Bs[cur][ks * 8][wn * 32 + j * 16], BSTRIDE);
                split_frag(b_hi[j], b_lo[j]);
            }
#pragma unroll
            for (int i = 0; i < 2; i++)
#pragma unroll
                for (int j = 0; j < 2; j++) {
                    wmma::mma_sync(c[i][j], a_hi[i], b_lo[j], c[i][j]);
                    wmma::mma_sync(c[i][j], a_lo[i], b_hi[j], c[i][j]);
                    wmma::mma_sync(c[i][j], a_hi[i], b_hi[j], c[i][j]);
                }
        }
        if (kt + 1 < nk) {
            int nxt = cur ^ 1;
            *(float4*)&As[nxt][ar0][ac0] = an0; *(float4*)&As[nxt][ar1][ac1] = an1;
            *(float4*)&Bs[nxt][br_][bc_] = bn0;
            __syncthreads();
        }
    }

#pragma unroll
    for (int i = 0; i < 2; i++) {
        int mm = m0 + wm * 32 + i * 16;   // query position s
        float* base = g_ctx + ((size_t)(b * SEQ + mm) * HID + h * HDIM);
#pragma unroll
        for (int j = 0; j < 2; j++)
            wmma::store_matrix_sync(base + wn * 32 + j * 16, c[i][j], HID, wmma::mem_row_major);
    }
}

// ---------------- launch ----------------
extern "C" void kernel_launch(void* const* d_in, const int* in_sizes, int n_in,
                              void* d_out, int out_size) {
    const float* x   = (const float*)d_in[0];
    const float* Wq  = (const float*)d_in[1];
    const float* Wk  = (const float*)d_in[2];
    const float* Wv  = (const float*)d_in[3];
    const float* Wo  = (const float*)d_in[4];
    const float* bo  = (const float*)d_in[5];
    const float* thr = (const float*)d_in[6];
    float* out = (float*)d_out;

    proj_kernel<<<dim3(HID/128, (NB*SEQ)/128, 3), 256>>>(x, Wq, Wk, Wv);
    scores_kernel<<<dim3(SEQ/128, SEQ/128, NBH), 256>>>();
    topk_softmax_kernel<<<NBH * SEQ, 256>>>(thr);
    av_kernel<<<dim3(1, SEQ/128, NBH), 256>>>();
    final_kernel<<<dim3(HID/128, (NB*SEQ)/128, 1), 256>>>(Wo, out);
    bias_kernel<<<(NB*SEQ*HID/4)/256, 256>>>(out, bo);
}

// round 8
// speedup vs baseline: 1.8249x; 1.8249x over previous
#include <cuda_runtime.h>
#include <cuda_bf16.h>
#include <mma.h>
#include <math.h>

using namespace nvcuda;

#define HID    1024
#define NHEADS 16
#define HDIM   64
#define NB     2
#define SEQ    2048
#define NBH    (NB*NHEADS)
#define KKEEP  1024

#define BKP 24   // 16 + 8 pad (48B rows: 16B-aligned, conflict-free ldmatrix)

typedef __nv_bfloat16 bf16;

// ---------------- scratch (allocation-free: __device__ globals) ----------------
__device__ float g_q[(size_t)NBH * SEQ * HDIM];
__device__ float g_k[(size_t)NBH * SEQ * HDIM];
__device__ float g_v[(size_t)NBH * SEQ * HDIM];
__device__ float g_p[(size_t)NBH * SEQ * SEQ];          // fp32 scores
__device__ float g_ctx[(size_t)NB * SEQ * HID];

__device__ bf16 g_x_hi[(size_t)NB*SEQ*HID],  g_x_lo[(size_t)NB*SEQ*HID];
__device__ bf16 g_wq_hi[HID*HID], g_wq_lo[HID*HID];
__device__ bf16 g_wk_hi[HID*HID], g_wk_lo[HID*HID];
__device__ bf16 g_wv_hi[HID*HID], g_wv_lo[HID*HID];
__device__ bf16 g_wo_hi[HID*HID], g_wo_lo[HID*HID];
__device__ bf16 g_q_hi[(size_t)NBH*SEQ*HDIM], g_q_lo[(size_t)NBH*SEQ*HDIM];
__device__ bf16 g_k_hi[(size_t)NBH*SEQ*HDIM], g_k_lo[(size_t)NBH*SEQ*HDIM];
__device__ bf16 g_v_hi[(size_t)NBH*SEQ*HDIM], g_v_lo[(size_t)NBH*SEQ*HDIM];
__device__ bf16 g_p_hi[(size_t)NBH*SEQ*SEQ],  g_p_lo[(size_t)NBH*SEQ*SEQ];   // probs hi/lo
__device__ bf16 g_c_hi[(size_t)NB*SEQ*HID],   g_c_lo[(size_t)NB*SEQ*HID];

// ---------------- helpers ----------------
__device__ __forceinline__ void split1(float f, bf16& h, bf16& l) {
    h = __float2bfloat16_rn(f);
    l = __float2bfloat16_rn(f - __bfloat162float(h));
}

__global__ void split_kernel(const float* __restrict__ src,
                             bf16* __restrict__ hi, bf16* __restrict__ lo, int n4) {
    int i = blockIdx.x * blockDim.x + threadIdx.x;
    if (i >= n4) return;
    float4 v = ((const float4*)src)[i];
    bf16 h0,l0,h1,l1,h2,l2,h3,l3;
    split1(v.x,h0,l0); split1(v.y,h1,l1); split1(v.z,h2,l2); split1(v.w,h3,l3);
    __nv_bfloat162* hp = (__nv_bfloat162*)hi;
    __nv_bfloat162* lp = (__nv_bfloat162*)lo;
    hp[2*i]   = __nv_bfloat162(h0,h1);
    hp[2*i+1] = __nv_bfloat162(h2,h3);
    lp[2*i]   = __nv_bfloat162(l0,l1);
    lp[2*i+1] = __nv_bfloat162(l2,l3);
}

// ---------------- reduces ----------------
__device__ __forceinline__ float warp_max_f(float v) {
#pragma unroll
    for (int o = 16; o > 0; o >>= 1) v = fmaxf(v, __shfl_xor_sync(0xffffffffu, v, o));
    return v;
}
__device__ __forceinline__ float warp_sum_f(float v) {
#pragma unroll
    for (int o = 16; o > 0; o >>= 1) v += __shfl_xor_sync(0xffffffffu, v, o);
    return v;
}
__device__ __forceinline__ float block_max_f(float v, float* sm) {
    v = warp_max_f(v);
    if ((threadIdx.x & 31) == 0) sm[threadIdx.x >> 5] = v;
    __syncthreads();
    if (threadIdx.x == 0) {
        float r = sm[0];
#pragma unroll
        for (int i = 1; i < 8; i++) r = fmaxf(r, sm[i]);
        sm[0] = r;
    }
    __syncthreads();
    v = sm[0];
    __syncthreads();
    return v;
}
__device__ __forceinline__ float block_sum_f(float v, float* sm) {
    v = warp_sum_f(v);
    if ((threadIdx.x & 31) == 0) sm[threadIdx.x >> 5] = v;
    __syncthreads();
    if (threadIdx.x == 0) {
        float r = sm[0];
#pragma unroll
        for (int i = 1; i < 8; i++) r += sm[i];
        sm[0] = r;
    }
    __syncthreads();
    v = sm[0];
    __syncthreads();
    return v;
}

// ===================================================================
// bf16x3 WMMA NT GEMM core: C(128x128) = A * B^T with A,B pre-split
// hi/lo bf16 in gmem. 8 warps (4m x 2n), warp tile 32x64, BK=16,
// double-buffered smem (exactly 48 KB). 3 MMAs per frag pair:
// hi*hi + hi*lo + lo*hi.
// ===================================================================
typedef wmma::fragment<wmma::accumulator, 16, 16, 16, float> Acc16;
typedef wmma::fragment<wmma::matrix_a, 16, 16, 16, bf16, wmma::row_major> ABf;
typedef wmma::fragment<wmma::matrix_b, 16, 16, 16, bf16, wmma::col_major> BBfCol;
typedef wmma::fragment<wmma::matrix_b, 16, 16, 16, bf16, wmma::row_major> BBfRow;

__device__ __forceinline__ void nt_bf16x3_gemm(
    const bf16* __restrict__ Ah, const bf16* __restrict__ Al,
    const bf16* __restrict__ Bh, const bf16* __restrict__ Bl,
    int K, int m0, int n0, Acc16 c[2][4])
{
    __shared__ alignas(16) bf16 Ash[2][128][BKP];
    __shared__ alignas(16) bf16 Asl[2][128][BKP];
    __shared__ alignas(16) bf16 Bsh[2][128][BKP];
    __shared__ alignas(16) bf16 Bsl[2][128][BKP];

    int tid  = threadIdx.x;
    int warp = tid >> 5;
    int wm = warp >> 1, wn = warp & 1;

#pragma unroll
    for (int i = 0; i < 2; i++)
#pragma unroll
        for (int j = 0; j < 4; j++)
            wmma::fill_fragment(c[i][j], 0.0f);

    int lrow = tid >> 1;            // 0..127
    int lseg = (tid & 1) << 3;      // 0 or 8

    {
        uint4 ah = *(const uint4*)(Ah + (size_t)(m0 + lrow) * K + lseg);
        uint4 al = *(const uint4*)(Al + (size_t)(m0 + lrow) * K + lseg);
        uint4 bh = *(const uint4*)(Bh + (size_t)(n0 + lrow) * K + lseg);
        uint4 bl = *(const uint4*)(Bl + (size_t)(n0 + lrow) * K + lseg);
        *(uint4*)&Ash[0][lrow][lseg] = ah; *(uint4*)&Asl[0][lrow][lseg] = al;
        *(uint4*)&Bsh[0][lrow][lseg] = bh; *(uint4*)&Bsl[0][lrow][lseg] = bl;
    }
    __syncthreads();

    const int nk = K >> 4;
    for (int kt = 0; kt < nk; kt++) {
        int cur = kt & 1;
        uint4 ah, al, bh, bl;
        if (kt + 1 < nk) {
            int k0 = (kt + 1) << 4;
            ah = *(const uint4*)(Ah + (size_t)(m0 + lrow) * K + k0 + lseg);
            al = *(const uint4*)(Al + (size_t)(m0 + lrow) * K + k0 + lseg);
            bh = *(const uint4*)(Bh + (size_t)(n0 + lrow) * K + k0 + lseg);
            bl = *(const uint4*)(Bl + (size_t)(n0 + lrow) * K + k0 + lseg);
        }
        ABf a_hi[2], a_lo[2];
        BBfCol b_hi[4], b_lo[4];
#pragma unroll
        for (int i = 0; i < 2; i++) {
            wmma::load_matrix_sync(a_hi[i], &Ash[cur][wm * 32 + i * 16][0], BKP);
            wmma::load_matrix_sync(a_lo[i], &Asl[cur][wm * 32 + i * 16][0], BKP);
        }
#pragma unroll
        for (int j = 0; j < 4; j++) {
            wmma::load_matrix_sync(b_hi[j], &Bsh[cur][wn * 64 + j * 16][0], BKP);
            wmma::load_matrix_sync(b_lo[j], &Bsl[cur][wn * 64 + j * 16][0], BKP);
        }
#pragma unroll
        for (int i = 0; i < 2; i++)
#pragma unroll
            for (int j = 0; j < 4; j++) {
                wmma::mma_sync(c[i][j], a_hi[i], b_hi[j], c[i][j]);
                wmma::mma_sync(c[i][j], a_hi[i], b_lo[j], c[i][j]);
                wmma::mma_sync(c[i][j], a_lo[i], b_hi[j], c[i][j]);
            }
        if (kt + 1 < nk) {
            int nxt = cur ^ 1;
            *(uint4*)&Ash[nxt][lrow][lseg] = ah; *(uint4*)&Asl[nxt][lrow][lseg] = al;
            *(uint4*)&Bsh[nxt][lrow][lseg] = bh; *(uint4*)&Bsl[nxt][lrow][lseg] = bl;
            __syncthreads();
        }
    }
}

// ---------------- GEMM 1: QKV projection -> scatter [B,H,S,D] fp32 ----------------
__global__ void __launch_bounds__(256) proj_kernel() {
    const bf16 *Wh, *Wl;
    float* outp;
    if (blockIdx.z == 0)      { Wh = g_wq_hi; Wl = g_wq_lo; outp = g_q; }
    else if (blockIdx.z == 1) { Wh = g_wk_hi; Wl = g_wk_lo; outp = g_k; }
    else                      { Wh = g_wv_hi; Wl = g_wv_lo; outp = g_v; }

    int m0 = blockIdx.y * 128, n0 = blockIdx.x * 128;
    Acc16 c[2][4];
    nt_bf16x3_gemm(g_x_hi, g_x_lo, Wh, Wl, HID, m0, n0, c);

    int warp = threadIdx.x >> 5;
    int wm = warp >> 1, wn = warp & 1;
    int h = (n0 + wn * 64) >> 6;
#pragma unroll
    for (int i = 0; i < 2; i++) {
        int mm = m0 + wm * 32 + i * 16;
        int b = mm >> 11, s = mm & (SEQ - 1);
        float* base = outp + (((size_t)(b * NHEADS + h) * SEQ + s) * HDIM);
#pragma unroll
        for (int j = 0; j < 4; j++)
            wmma::store_matrix_sync(base + j * 16, c[i][j], HDIM, wmma::mem_row_major);
    }
}

// ---------------- GEMM 2: scores = Q K^T / 8 ----------------
__global__ void __launch_bounds__(256) scores_kernel() {
    int bh = blockIdx.z;
    const bf16* qh = g_q_hi + (size_t)bh * SEQ * HDIM;
    const bf16* ql = g_q_lo + (size_t)bh * SEQ * HDIM;
    const bf16* kh = g_k_hi + (size_t)bh * SEQ * HDIM;
    const bf16* kl = g_k_lo + (size_t)bh * SEQ * HDIM;
    float* C = g_p + (size_t)bh * SEQ * SEQ;

    int m0 = blockIdx.y * 128, n0 = blockIdx.x * 128;
    Acc16 c[2][4];
    nt_bf16x3_gemm(qh, ql, kh, kl, HDIM, m0, n0, c);

    int warp = threadIdx.x >> 5;
    int wm = warp >> 1, wn = warp & 1;
#pragma unroll
    for (int i = 0; i < 2; i++) {
        int mm = m0 + wm * 32 + i * 16;
#pragma unroll
        for (int j = 0; j < 4; j++) {
#pragma unroll
            for (int t = 0; t < c[i][j].num_elements; t++) c[i][j].x[t] *= 0.125f;
            wmma::store_matrix_sync(C + (size_t)mm * SEQ + n0 + wn * 64 + j * 16,
                                    c[i][j], SEQ, wmma::mem_row_major);
        }
    }
}

// ---------------- GEMM 4: out = ctx @ Wo^T ----------------
__global__ void __launch_bounds__(256) final_kernel(float* __restrict__ out) {
    int m0 = blockIdx.y * 128, n0 = blockIdx.x * 128;
    Acc16 c[2][4];
    nt_bf16x3_gemm(g_c_hi, g_c_lo, g_wo_hi, g_wo_lo, HID, m0, n0, c);

    int warp = threadIdx.x >> 5;
    int wm = warp >> 1, wn = warp & 1;
#pragma unroll
    for (int i = 0; i < 2; i++) {
        int mm = m0 + wm * 32 + i * 16;
#pragma unroll
        for (int j = 0; j < 4; j++)
            wmma::store_matrix_sync(out + (size_t)mm * HID + n0 + wn * 64 + j * 16,
                                    c[i][j], HID, wmma::mem_row_major);
    }
}

__global__ void bias_kernel(float* __restrict__ out, const float* __restrict__ bo) {
    int i = blockIdx.x * blockDim.x + threadIdx.x;
    float4 v = ((float4*)out)[i];
    float4 b = ((const float4*)bo)[i & 255];
    v.x += b.x; v.y += b.y; v.z += b.z; v.w += b.w;
    ((float4*)out)[i] = v;
}

// ---------------- kernel 3: exact top-k + threshold + softmax, writes P hi/lo ----------------
__global__ void __launch_bounds__(256) topk_softmax_kernel(const float* __restrict__ thr_ptr) {
    __shared__ unsigned hist[2048];
    __shared__ unsigned chunk[257];
    __shared__ float smf[8];
    __shared__ unsigned s_bin, s_kr;

    size_t row = blockIdx.x;
    const float* p = g_p + row * SEQ;
    bf16* ph = g_p_hi + row * SEQ;
    bf16* pl = g_p_lo + row * SEQ;
    int tid = threadIdx.x;

    float v[8];
    unsigned key[8];
    bool act[8];
#pragma unroll
    for (int i = 0; i < 8; i++) {
        v[i] = p[tid + (i << 8)];
        unsigned bb = __float_as_uint(v[i]);
        key[i] = (bb & 0x80000000u) ? ~bb : (bb | 0x80000000u);
        act[i] = true;
    }

    float lm = v[0];
#pragma unroll
    for (int i = 1; i < 8; i++) lm = fmaxf(lm, v[i]);
    float m = block_max_f(lm, smf);

    unsigned Kr = KKEEP;
    unsigned prefixKey = 0;

#pragma unroll
    for (int lvl = 0; lvl < 3; lvl++) {
        const int shift = (lvl == 0) ? 21 : (lvl == 1) ? 10 : 0;
        const unsigned mask = (lvl == 2) ? 1023u : 2047u;

        for (int i = tid; i < 2048; i += 256) hist[i] = 0u;
        __syncthreads();
#pragma unroll
        for (int i = 0; i < 8; i++)
            if (act[i]) atomicAdd(&hist[(key[i] >> shift) & mask], 1u);
        __syncthreads();

        unsigned cs = 0;
#pragma unroll
        for (int j = 0; j < 8; j++) cs += hist[(tid << 3) + j];
        chunk[tid] = cs;
        if (tid == 0) chunk[256] = 0u;
        __syncthreads();

        for (int off = 1; off < 256; off <<= 1) {
            unsigned add = (tid + off < 256) ? chunk[tid + off] : 0u;
            __syncthreads();
            chunk[tid] += add;
            __syncthreads();
        }

        unsigned sfx  = chunk[tid];
        unsigned sfxn = chunk[tid + 1];
        if (sfx >= Kr && sfxn < Kr) {
            unsigned cum = sfxn;
#pragma unroll
            for (int j = 7; j >= 0; j--) {
                unsigned h = hist[(tid << 3) + j];
                cum += h;
                if (cum >= Kr) {
                    s_bin = (tid << 3) + j;
                    s_kr  = Kr - (cum - h);
                    break;
                }
            }
        }
        __syncthreads();
        unsigned b = s_bin;
        Kr = s_kr;
        prefixKey |= b << shift;
        if (lvl < 2) {
#pragma unroll
            for (int i = 0; i < 8; i++)
                act[i] = act[i] && (((key[i] >> shift) & mask) == b);
        }
        __syncthreads();
    }

    float kth = __uint_as_float((prefixKey & 0x80000000u) ? (prefixKey ^ 0x80000000u)
                                                          : ~prefixKey);

    float thr = thr_ptr[0];
    thr = fminf(fmaxf(thr, 0.0f), 1.0f);
    float teff = fmaxf(kth, thr);

    float e[8];
    float ls = 0.0f;
#pragma unroll
    for (int i = 0; i < 8; i++) {
        e[i] = (v[i] >= teff) ? expf(v[i] - m) : 0.0f;
        ls += e[i];
    }
    float s = block_sum_f(ls, smf);
    float inv = 1.0f / s;
#pragma unroll
    for (int i = 0; i < 8; i++) {
        float prob = e[i] * inv;
        bf16 h, l;
        split1(prob, h, l);
        ph[tid + (i << 8)] = h;
        pl[tid + (i << 8)] = l;
    }
}

// ---------------- GEMM 3 (NN, bf16x3): ctx = P @ V ----------------
// Block tile 128x64, 8 warps (4m x 2n), warp tile 32x32, BK=16.
#define BVP 72
__global__ void __launch_bounds__(256) av_kernel() {
    int bh = blockIdx.z;
    int b = bh >> 4, h = bh & 15;
    const bf16* Ph = g_p_hi + (size_t)bh * SEQ * SEQ;
    const bf16* Pl = g_p_lo + (size_t)bh * SEQ * SEQ;
    const bf16* Vh = g_v_hi + (size_t)bh * SEQ * HDIM;
    const bf16* Vl = g_v_lo + (size_t)bh * SEQ * HDIM;

    __shared__ alignas(16) bf16 Ash[2][128][BKP];
    __shared__ alignas(16) bf16 Asl[2][128][BKP];
    __shared__ alignas(16) bf16 Bsh[2][16][BVP];
    __shared__ alignas(16) bf16 Bsl[2][16][BVP];

    int tid  = threadIdx.x;
    int warp = tid >> 5;
    int wm = warp >> 1, wn = warp & 1;
    int m0 = blockIdx.y * 128;

    Acc16 c[2][2];
#pragma unroll
    for (int i = 0; i < 2; i++)
#pragma unroll
        for (int j = 0; j < 2; j++)
            wmma::fill_fragment(c[i][j], 0.0f);

    int lrow = tid >> 1, lseg = (tid & 1) << 3;         // P loader
    int vrow = (tid & 127) >> 3, vseg = ((tid & 127) & 7) << 3;  // V loader: 16x64
    bool v_hi_half = (tid < 128);

    {
        uint4 ah = *(const uint4*)(Ph + (size_t)(m0 + lrow) * SEQ + lseg);
        uint4 al = *(const uint4*)(Pl + (size_t)(m0 + lrow) * SEQ + lseg);
        *(uint4*)&Ash[0][lrow][lseg] = ah; *(uint4*)&Asl[0][lrow][lseg] = al;
        const bf16* vsrc = v_hi_half ? Vh : Vl;
        uint4 bv = *(const uint4*)(vsrc + (size_t)vrow * HDIM + vseg);
        if (v_hi_half) *(uint4*)&Bsh[0][vrow][vseg] = bv;
        else           *(uint4*)&Bsl[0][vrow][vseg] = bv;
    }
    __syncthreads();

    const int nk = SEQ >> 4;
    for (int kt = 0; kt < nk; kt++) {
        int cur = kt & 1;
        uint4 ah, al, bv;
        if (kt + 1 < nk) {
            int k0 = (kt + 1) << 4;
            ah = *(const uint4*)(Ph + (size_t)(m0 + lrow) * SEQ + k0 + lseg);
            al = *(const uint4*)(Pl + (size_t)(m0 + lrow) * SEQ + k0 + lseg);
            const bf16* vsrc = v_hi_half ? Vh : Vl;
            bv = *(const uint4*)(vsrc + (size_t)(k0 + vrow) * HDIM + vseg);
        }
        ABf a_hi[2], a_lo[2];
        BBfRow b_hi[2], b_lo[2];
#pragma unroll
        for (int i = 0; i < 2; i++) {
            wmma::load_matrix_sync(a_hi[i], &Ash[cur][wm * 32 + i * 16][0], BKP);
            wmma::load_matrix_sync(a_lo[i], &Asl[cur][wm * 32 + i * 16][0], BKP);
        }
#pragma unroll
        for (int j = 0; j < 2; j++) {
            wmma::load_matrix_sync(b_hi[j], &Bsh[cur][0][wn * 32 + j * 16], BVP);
            wmma::load_matrix_sync(b_lo[j], &Bsl[cur][0][wn * 32 + j * 16], BVP);
        }
#pragma unroll
        for (int i = 0; i < 2; i++)
#pragma unroll
            for (int j = 0; j < 2; j++) {
                wmma::mma_sync(c[i][j], a_hi[i], b_hi[j], c[i][j]);
                wmma::mma_sync(c[i][j], a_hi[i], b_lo[j], c[i][j]);
                wmma::mma_sync(c[i][j], a_lo[i], b_hi[j], c[i][j]);
            }
        if (kt + 1 < nk) {
            int nxt = cur ^ 1;
            *(uint4*)&Ash[nxt][lrow][lseg] = ah; *(uint4*)&Asl[nxt][lrow][lseg] = al;
            if (v_hi_half) *(uint4*)&Bsh[nxt][vrow][vseg] = bv;
            else           *(uint4*)&Bsl[nxt][vrow][vseg] = bv;
            __syncthreads();
        }
    }

#pragma unroll
    for (int i = 0; i < 2; i++) {
        int mm = m0 + wm * 32 + i * 16;
        float* base = g_ctx + ((size_t)(b * SEQ + mm) * HID + h * HDIM);
#pragma unroll
        for (int j = 0; j < 2; j++)
            wmma::store_matrix_sync(base + wn * 32 + j * 16, c[i][j], HID, wmma::mem_row_major);
    }
}

// ---------------- launch ----------------
extern "C" void kernel_launch(void* const* d_in, const int* in_sizes, int n_in,
                              void* d_out, int out_size) {
    const float* x   = (const float*)d_in[0];
    const float* Wq  = (const float*)d_in[1];
    const float* Wk  = (const float*)d_in[2];
    const float* Wv  = (const float*)d_in[3];
    const float* Wo  = (const float*)d_in[4];
    const float* bo  = (const float*)d_in[5];
    const float* thr = (const float*)d_in[6];
    float* out = (float*)d_out;

    // Resolve device-symbol addresses host-side once per call (cheap, capturable-safe).
    bf16 *xh, *xl, *wqh, *wql, *wkh, *wkl, *wvh, *wvl, *woh, *wol;
    bf16 *qh, *ql, *kh, *kl, *vh, *vl, *ch, *cl;
    float *qf, *kf, *vf, *cf;
    cudaGetSymbolAddress((void**)&xh,  g_x_hi);  cudaGetSymbolAddress((void**)&xl,  g_x_lo);
    cudaGetSymbolAddress((void**)&wqh, g_wq_hi); cudaGetSymbolAddress((void**)&wql, g_wq_lo);
    cudaGetSymbolAddress((void**)&wkh, g_wk_hi); cudaGetSymbolAddress((void**)&wkl, g_wk_lo);
    cudaGetSymbolAddress((void**)&wvh, g_wv_hi); cudaGetSymbolAddress((void**)&wvl, g_wv_lo);
    cudaGetSymbolAddress((void**)&woh, g_wo_hi); cudaGetSymbolAddress((void**)&wol, g_wo_lo);
    cudaGetSymbolAddress((void**)&qh,  g_q_hi);  cudaGetSymbolAddress((void**)&ql,  g_q_lo);
    cudaGetSymbolAddress((void**)&kh,  g_k_hi);  cudaGetSymbolAddress((void**)&kl,  g_k_lo);
    cudaGetSymbolAddress((void**)&vh,  g_v_hi);  cudaGetSymbolAddress((void**)&vl,  g_v_lo);
    cudaGetSymbolAddress((void**)&ch,  g_c_hi);  cudaGetSymbolAddress((void**)&cl,  g_c_lo);
    cudaGetSymbolAddress((void**)&qf,  g_q);     cudaGetSymbolAddress((void**)&kf,  g_k);
    cudaGetSymbolAddress((void**)&vf,  g_v);     cudaGetSymbolAddress((void**)&cf,  g_ctx);

    const int QKV = NBH * SEQ * HDIM;   // 4M elems
    const int XN  = NB * SEQ * HID;     // 2M elems
    const int WN  = HID * HID;          // 1M elems

    // split inputs
    split_kernel<<<(XN/4)/256, 256>>>(x,  xh,  xl,  XN/4);
    split_kernel<<<(WN/4)/256, 256>>>(Wq, wqh, wql, WN/4);
    split_kernel<<<(WN/4)/256, 256>>>(Wk, wkh, wkl, WN/4);
    split_kernel<<<(WN/4)/256, 256>>>(Wv, wvh, wvl, WN/4);
    split_kernel<<<(WN/4)/256, 256>>>(Wo, woh, wol, WN/4);

    proj_kernel<<<dim3(HID/128, (NB*SEQ)/128, 3), 256>>>();

    split_kernel<<<(QKV/4)/256, 256>>>(qf, qh, ql, QKV/4);
    split_kernel<<<(QKV/4)/256, 256>>>(kf, kh, kl, QKV/4);
    split_kernel<<<(QKV/4)/256, 256>>>(vf, vh, vl, QKV/4);

    scores_kernel<<<dim3(SEQ/128, SEQ/128, NBH), 256>>>();
    topk_softmax_kernel<<<NBH * SEQ, 256>>>(thr);
    av_kernel<<<dim3(1, SEQ/128, NBH), 256>>>();

    split_kernel<<<(XN/4)/256, 256>>>(cf, ch, cl, XN/4);

    final_kernel<<<dim3(HID/128, (NB*SEQ)/128, 1), 256>>>(out);
    bias_kernel<<<(NB*SEQ*HID/4)/256, 256>>>(out, bo);
}